// round 9
// baseline (speedup 1.0000x reference)
#include <cuda_runtime.h>
#include <cstdint>
#include <cstddef>

// Problem constants
#define BS_N      2048
#define K1        9408
#define N1        1024
#define D1        2048
#define NCLS      65
#define WFC_COLS  3072   // D1 + N1

// GEMM1 tiling
#define BM 128
#define BN 128
#define BK 32
#define STRIDE 36        // BK padded: 36 floats = 144B (16B-aligned rows, conflict-free frag loads)
#define KT_ITERS (K1 / BK)   // 294

// Scratch (static device arrays — no allocation allowed)
__device__ float g_scratch[16 * N1];   // per-row-block partial column sums of relu(z2p)
__device__ float g_const[NCLS];        // S2[c] + 2048*b_fc[c]

// ---------------------------------------------------------------------------
// helpers
// ---------------------------------------------------------------------------
__device__ __forceinline__ uint32_t f2tf(float x) {
    uint32_t r;
    asm volatile("cvt.rna.tf32.f32 %0, %1;" : "=r"(r) : "f"(x));
    return r;
}

__device__ __forceinline__ void cp_async16(float* s, const float* g) {
    uint32_t sa = (uint32_t)__cvta_generic_to_shared(s);
    asm volatile("cp.async.cg.shared.global [%0], [%1], 16;\n" :: "r"(sa), "l"(g));
}

#define MMA_TF32(d, a, b)                                                      \
    asm volatile(                                                              \
        "mma.sync.aligned.m16n8k8.row.col.f32.tf32.tf32.f32 "                  \
        "{%0,%1,%2,%3}, {%4,%5,%6,%7}, {%8,%9}, {%0,%1,%2,%3};\n"              \
        : "+f"(d[0]), "+f"(d[1]), "+f"(d[2]), "+f"(d[3])                       \
        : "r"(a[0]), "r"(a[1]), "r"(a[2]), "r"(a[3]), "r"(b[0]), "r"(b[1]))

// ---------------------------------------------------------------------------
// Kernel 1: Y = relu(z2f @ W_proj^T + b_proj); column-partial-sums -> g_scratch
// grid (8 N-tiles, 16 M-tiles), 256 threads, tf32 mma, cp.async double buffer
// ---------------------------------------------------------------------------
__device__ __forceinline__ void load_tiles(float* As, float* Bs,
                                           const float* __restrict__ A,
                                           const float* __restrict__ W,
                                           int bm, int bn, int k0, int tid) {
#pragma unroll
    for (int q = 0; q < 4; ++q) {
        int idx = tid + 256 * q;
        int row = idx >> 3, kc = idx & 7;
        cp_async16(As + row * STRIDE + kc * 4,
                   A + (size_t)(bm * BM + row) * K1 + k0 + kc * 4);
    }
#pragma unroll
    for (int q = 0; q < 4; ++q) {
        int idx = tid + 256 * q;
        int row = idx >> 3, kc = idx & 7;
        cp_async16(Bs + row * STRIDE + kc * 4,
                   W + (size_t)(bn * BN + row) * K1 + k0 + kc * 4);
    }
}

__global__ __launch_bounds__(256, 1)
void gemm1_kernel(const float* __restrict__ A,     // z2 flattened [2048, 9408]
                  const float* __restrict__ W,     // W_proj [1024, 9408]
                  const float* __restrict__ bias)  // b_proj [1024]
{
    extern __shared__ float smem[];
    float* As = smem;                                // 2 stages x [BM][STRIDE]
    float* Bs = smem + 2 * BM * STRIDE;              // 2 stages x [BN][STRIDE]
    float* bsm    = smem + 2 * (BM + BN) * STRIDE;   // [BN]
    float* colsum = bsm + BN;                        // [BN]

    const int tid = threadIdx.x;
    const int bn = blockIdx.x, bm = blockIdx.y;

    if (tid < BN) bsm[tid] = bias[bn * BN + tid];

    const int warp = tid >> 5, lane = tid & 31;
    const int gid = lane >> 2, tig = lane & 3;
    const int mbase = (warp & 1) * 64;
    const int nbase = (warp >> 1) * 32;

    float acc[4][4][4] = {};

    load_tiles(As, Bs, A, W, bm, bn, 0, tid);
    asm volatile("cp.async.commit_group;\n");

    for (int kt = 0; kt < KT_ITERS; ++kt) {
        if (kt + 1 < KT_ITERS) {
            int ns = (kt + 1) & 1;
            load_tiles(As + ns * BM * STRIDE, Bs + ns * BN * STRIDE,
                       A, W, bm, bn, (kt + 1) * BK, tid);
            asm volatile("cp.async.commit_group;\n");
            asm volatile("cp.async.wait_group 1;\n");
        } else {
            asm volatile("cp.async.wait_group 0;\n");
        }
        __syncthreads();

        const int s = kt & 1;
        const float* Ast = As + s * BM * STRIDE;
        const float* Bst = Bs + s * BN * STRIDE;

#pragma unroll
        for (int ks = 0; ks < 4; ++ks) {
            const int kk = ks * 8 + tig;
            uint32_t af[4][4];
            uint32_t bf[4][2];
#pragma unroll
            for (int mi = 0; mi < 4; ++mi) {
                const float* p = Ast + (mbase + mi * 16 + gid) * STRIDE + kk;
                af[mi][0] = f2tf(p[0]);
                af[mi][1] = f2tf(p[8 * STRIDE]);
                af[mi][2] = f2tf(p[4]);
                af[mi][3] = f2tf(p[8 * STRIDE + 4]);
            }
#pragma unroll
            for (int ni = 0; ni < 4; ++ni) {
                const float* p = Bst + (nbase + ni * 8 + gid) * STRIDE + kk;
                bf[ni][0] = f2tf(p[0]);
                bf[ni][1] = f2tf(p[4]);
            }
#pragma unroll
            for (int mi = 0; mi < 4; ++mi)
#pragma unroll
                for (int ni = 0; ni < 4; ++ni)
                    MMA_TF32(acc[mi][ni], af[mi], bf[ni]);
        }
        __syncthreads();
    }

    // Epilogue: relu(acc + bias), reduce columns over the 128 rows of this tile
    if (tid < BN) colsum[tid] = 0.f;
    __syncthreads();

#pragma unroll
    for (int ni = 0; ni < 4; ++ni) {
#pragma unroll
        for (int p = 0; p < 2; ++p) {
            const int col = nbase + ni * 8 + 2 * tig + p;
            const float b = bsm[col];
            float s = 0.f;
#pragma unroll
            for (int mi = 0; mi < 4; ++mi) {
                s += fmaxf(acc[mi][ni][p] + b, 0.f);
                s += fmaxf(acc[mi][ni][2 + p] + b, 0.f);
            }
            atomicAdd(&colsum[col], s);
        }
    }
    __syncthreads();
    if (tid < BN) g_scratch[bm * N1 + bn * BN + tid] = colsum[tid];
}

// ---------------------------------------------------------------------------
// Kernel 2: t[k] = sum over 16 row-blocks; g_const[c] = t.W2[c] + 2048*b_fc[c]
// ---------------------------------------------------------------------------
__global__ void reduce_kernel(const float* __restrict__ W_fc,
                              const float* __restrict__ b_fc) {
    __shared__ float t[N1];
    const int tid = threadIdx.x;
    for (int k = tid; k < N1; k += 256) {
        float s = 0.f;
#pragma unroll
        for (int bm = 0; bm < 16; ++bm) s += g_scratch[bm * N1 + k];
        t[k] = s;
    }
    __syncthreads();

    const int w = tid >> 5, lane = tid & 31;
    for (int c = w; c < NCLS; c += 8) {
        const float* wr = W_fc + (size_t)c * WFC_COLS + D1;
        float s = 0.f;
        for (int k = lane; k < N1; k += 32) s += t[k] * wr[k];
#pragma unroll
        for (int o = 16; o; o >>= 1) s += __shfl_xor_sync(0xffffffffu, s, o);
        if (lane == 0) g_const[c] = s + 2048.f * b_fc[c];
    }
}

// ---------------------------------------------------------------------------
// Kernel 3: out[i,c] = 2048 * (z1 @ W1^T)[i,c] + g_const[c]   (fp32, exact)
// grid 128 blocks x (16,16) threads; 16 rows/block, thread = 4 cols (+col 64)
// ---------------------------------------------------------------------------
__global__ __launch_bounds__(256, 2)
void fc_kernel(const float* __restrict__ z1, const float* __restrict__ W_fc,
               float* __restrict__ out) {
    __shared__ __align__(16) float Wt[64 * 72];   // [kk][c], c padded to 72
    __shared__ float z1s[16 * 65];                // [row][kk], pitch 65

    const int tx = threadIdx.x;   // 0..15 -> 4 consecutive cols
    const int ty = threadIdx.y;   // 0..15 -> row
    const int tid = ty * 16 + tx;
    const int rbase = blockIdx.x * 16;

    float a0 = 0.f, a1 = 0.f, a2 = 0.f, a3 = 0.f;
    float e0 = 0.f;  // column 64 (tx == 0 only)

    for (int kc = 0; kc < 32; ++kc) {
        const int k0 = kc * 64;
        __syncthreads();
        for (int i = tid; i < 16 * 64; i += 256) {
            const int r = i >> 6, kk = i & 63;
            z1s[r * 65 + kk] = z1[(size_t)(rbase + r) * D1 + k0 + kk];
        }
        for (int i = tid; i < NCLS * 64; i += 256) {
            const int c = i >> 6, kk = i & 63;
            Wt[kk * 72 + c] = W_fc[(size_t)c * WFC_COLS + k0 + kk];
        }
        __syncthreads();

#pragma unroll 4
        for (int kk = 0; kk < 64; ++kk) {
            const float av = z1s[ty * 65 + kk];
            const float4 wv = *reinterpret_cast<const float4*>(&Wt[kk * 72 + tx * 4]);
            a0 += av * wv.x;
            a1 += av * wv.y;
            a2 += av * wv.z;
            a3 += av * wv.w;
            if (tx == 0) e0 += av * Wt[kk * 72 + 64];
        }
    }

    const int row = rbase + ty;
    float* orow = out + (size_t)row * NCLS;
    const int c0 = tx * 4;
    orow[c0 + 0] = 2048.f * a0 + g_const[c0 + 0];
    orow[c0 + 1] = 2048.f * a1 + g_const[c0 + 1];
    orow[c0 + 2] = 2048.f * a2 + g_const[c0 + 2];
    orow[c0 + 3] = 2048.f * a3 + g_const[c0 + 3];
    if (tx == 0) orow[64] = 2048.f * e0 + g_const[64];
}

// ---------------------------------------------------------------------------
// launch
// ---------------------------------------------------------------------------
#define GEMM1_SMEM ((2 * (BM + BN) * STRIDE + 2 * BN) * (int)sizeof(float))  // 74752 B

extern "C" void kernel_launch(void* const* d_in, const int* in_sizes, int n_in,
                              void* d_out, int out_size) {
    const float *z1 = nullptr, *z2 = nullptr, *Wp = nullptr, *bp = nullptr,
                *Wf = nullptr, *bfc = nullptr;
    for (int i = 0; i < n_in; ++i) {
        switch (in_sizes[i]) {
            case BS_N * D1:     z1  = (const float*)d_in[i]; break;  // 4194304
            case BS_N * K1:     z2  = (const float*)d_in[i]; break;  // 19267584
            case N1 * K1:       Wp  = (const float*)d_in[i]; break;  // 9633792
            case N1:            bp  = (const float*)d_in[i]; break;  // 1024
            case NCLS * WFC_COLS: Wf = (const float*)d_in[i]; break; // 199680
            case NCLS:          bfc = (const float*)d_in[i]; break;  // 65
            default: break;
        }
    }

    cudaFuncSetAttribute(gemm1_kernel,
                         cudaFuncAttributeMaxDynamicSharedMemorySize, GEMM1_SMEM);

    gemm1_kernel<<<dim3(8, 16), 256, GEMM1_SMEM>>>(z2, Wp, bp);
    reduce_kernel<<<1, 256>>>(Wf, bfc);
    fc_kernel<<<128, dim3(16, 16)>>>(z1, Wf, (float*)d_out);
}

// round 12
// speedup vs baseline: 1.2347x; 1.2347x over previous
#include <cuda_runtime.h>
#include <cstdint>
#include <cstddef>

// Problem constants
#define BS_N      2048
#define K1        9408
#define N1        1024
#define D1        2048
#define NCLS      65
#define WFC_COLS  3072   // D1 + N1

// GEMM1 tiling (BN=64 -> 2 CTAs/SM, 3-stage pipeline)
#define BM 128
#define BN 64
#define BK 32
#define STRIDE 36
#define KT_ITERS (K1 / BK)   // 294

// FC (s1) MMA tiling: M=2048, N=72 (65 padded), K=2048 split 8 ways
#define FC_BN 72
#define FC_KSPLIT 8
#define FC_KCHUNK (D1 / FC_KSPLIT)    // 256
#define FC_KT (FC_KCHUNK / BK)        // 8

// Scratch (static device arrays — no allocation allowed)
__device__ float g_scratch[16 * N1];             // per-row-block colsums of relu(z2p)
__device__ float g_const[NCLS];                  // S2[c] + 2048*b_fc[c]
__device__ float g_fcpart[FC_KSPLIT * BS_N * FC_BN];  // s1 partials (4.7MB)

// ---------------------------------------------------------------------------
// helpers
// ---------------------------------------------------------------------------
__device__ __forceinline__ uint32_t f2tf(float x) {
    uint32_t r;
    asm volatile("cvt.rna.tf32.f32 %0, %1;" : "=r"(r) : "f"(x));
    return r;
}

__device__ __forceinline__ void cp_async16(float* s, const float* g) {
    uint32_t sa = (uint32_t)__cvta_generic_to_shared(s);
    asm volatile("cp.async.cg.shared.global [%0], [%1], 16;\n" :: "r"(sa), "l"(g));
}

#define MMA_TF32(d, a, b)                                                      \
    asm volatile(                                                              \
        "mma.sync.aligned.m16n8k8.row.col.f32.tf32.tf32.f32 "                  \
        "{%0,%1,%2,%3}, {%4,%5,%6,%7}, {%8,%9}, {%0,%1,%2,%3};\n"              \
        : "+f"(d[0]), "+f"(d[1]), "+f"(d[2]), "+f"(d[3])                       \
        : "r"(a[0]), "r"(a[1]), "r"(a[2]), "r"(a[3]), "r"(b[0]), "r"(b[1]))

// ---------------------------------------------------------------------------
// Kernel 1: relu(z2f @ W_proj^T + b) column sums. grid (16 bn, 16 bm), 256 thr
// 3-stage cp.async, 2 CTAs/SM.
// ---------------------------------------------------------------------------
__device__ __forceinline__ void g1_load(float* As, float* Bs,
                                        const float* __restrict__ A,
                                        const float* __restrict__ W,
                                        int bm, int bn, int k0, int tid) {
#pragma unroll
    for (int q = 0; q < 4; ++q) {              // A: 128 rows x 8 quads
        int idx = tid + 256 * q;
        int row = idx >> 3, kc = idx & 7;
        cp_async16(As + row * STRIDE + kc * 4,
                   A + (size_t)(bm * BM + row) * K1 + k0 + kc * 4);
    }
#pragma unroll
    for (int q = 0; q < 2; ++q) {              // B: 64 rows x 8 quads
        int idx = tid + 256 * q;
        int row = idx >> 3, kc = idx & 7;
        cp_async16(Bs + row * STRIDE + kc * 4,
                   W + (size_t)(bn * BN + row) * K1 + k0 + kc * 4);
    }
}

__global__ __launch_bounds__(256, 2)
void gemm1_kernel(const float* __restrict__ A,     // z2 [2048, 9408]
                  const float* __restrict__ W,     // W_proj [1024, 9408]
                  const float* __restrict__ bias)  // b_proj [1024]
{
    extern __shared__ float smem[];
    float* As = smem;                                 // 3 x [BM][STRIDE]
    float* Bs = smem + 3 * BM * STRIDE;               // 3 x [BN][STRIDE]
    float* bsm    = smem + 3 * (BM + BN) * STRIDE;    // [BN]
    float* colsum = bsm + BN;                         // [BN]

    const int tid = threadIdx.x;
    const int bn = blockIdx.x, bm = blockIdx.y;

    if (tid < BN) bsm[tid] = bias[bn * BN + tid];

    const int warp = tid >> 5, lane = tid & 31;
    const int gid = lane >> 2, tig = lane & 3;
    const int mbase = (warp & 1) * 64;      // 2 m-warps
    const int nbase = (warp >> 1) * 16;     // 4 n-warps

    float acc[4][2][4] = {};

    g1_load(As, Bs, A, W, bm, bn, 0, tid);
    asm volatile("cp.async.commit_group;\n");
    g1_load(As + BM * STRIDE, Bs + BN * STRIDE, A, W, bm, bn, BK, tid);
    asm volatile("cp.async.commit_group;\n");

    for (int kt = 0; kt < KT_ITERS; ++kt) {
        if (kt + 2 < KT_ITERS) {
            asm volatile("cp.async.wait_group 1;\n");
        } else {
            asm volatile("cp.async.wait_group 0;\n");
        }
        __syncthreads();

        if (kt + 2 < KT_ITERS) {
            int ns = (kt + 2) % 3;
            g1_load(As + ns * BM * STRIDE, Bs + ns * BN * STRIDE,
                    A, W, bm, bn, (kt + 2) * BK, tid);
            asm volatile("cp.async.commit_group;\n");
        }

        const int s = kt % 3;
        const float* Ast = As + s * BM * STRIDE;
        const float* Bst = Bs + s * BN * STRIDE;

#pragma unroll
        for (int ks = 0; ks < 4; ++ks) {
            const int kk = ks * 8 + tig;
            uint32_t af[4][4];
            uint32_t bf[2][2];
#pragma unroll
            for (int mi = 0; mi < 4; ++mi) {
                const float* p = Ast + (mbase + mi * 16 + gid) * STRIDE + kk;
                af[mi][0] = f2tf(p[0]);
                af[mi][1] = f2tf(p[8 * STRIDE]);
                af[mi][2] = f2tf(p[4]);
                af[mi][3] = f2tf(p[8 * STRIDE + 4]);
            }
#pragma unroll
            for (int ni = 0; ni < 2; ++ni) {
                const float* p = Bst + (nbase + ni * 8 + gid) * STRIDE + kk;
                bf[ni][0] = f2tf(p[0]);
                bf[ni][1] = f2tf(p[4]);
            }
#pragma unroll
            for (int mi = 0; mi < 4; ++mi)
#pragma unroll
                for (int ni = 0; ni < 2; ++ni)
                    MMA_TF32(acc[mi][ni], af[mi], bf[ni]);
        }
        __syncthreads();
    }

    // Epilogue: relu(acc+bias), reduce over 128 rows
    if (tid < BN) colsum[tid] = 0.f;
    __syncthreads();

#pragma unroll
    for (int ni = 0; ni < 2; ++ni) {
#pragma unroll
        for (int p = 0; p < 2; ++p) {
            const int col = nbase + ni * 8 + 2 * tig + p;
            const float b = bsm[col];
            float s = 0.f;
#pragma unroll
            for (int mi = 0; mi < 4; ++mi) {
                s += fmaxf(acc[mi][ni][p] + b, 0.f);
                s += fmaxf(acc[mi][ni][2 + p] + b, 0.f);
            }
            atomicAdd(&colsum[col], s);
        }
    }
    __syncthreads();
    if (tid < BN) g_scratch[bm * N1 + bn * BN + tid] = colsum[tid];
}

// ---------------------------------------------------------------------------
// Kernel 2 (s1 via tf32 MMA): grid (8 ksplit, 16 bm), 256 thr, 2-stage.
// Each CTA: 128 rows x 72 cols (65 valid) over K-chunk 256. Partials->scratch.
// ---------------------------------------------------------------------------
__device__ __forceinline__ void fc_load(float* As, float* Bs,
                                        const float* __restrict__ z1,
                                        const float* __restrict__ Wf,
                                        int rbase, int k0, int tid) {
#pragma unroll
    for (int q = 0; q < 4; ++q) {              // A: 128 rows x 8 quads
        int idx = tid + 256 * q;
        int row = idx >> 3, kc = idx & 7;
        cp_async16(As + row * STRIDE + kc * 4,
                   z1 + (size_t)(rbase + row) * D1 + k0 + kc * 4);
    }
#pragma unroll
    for (int q = 0; q < 3; ++q) {              // B: 72 rows x 8 quads = 576
        int idx = tid + 256 * q;
        if (idx < FC_BN * 8) {
            int row = idx >> 3, kc = idx & 7;
            int c = row < NCLS ? row : NCLS - 1;   // clamp pad rows (in-bounds)
            cp_async16(Bs + row * STRIDE + kc * 4,
                       Wf + (size_t)c * WFC_COLS + k0 + kc * 4);
        }
    }
}

__global__ __launch_bounds__(256, 2)
void fc_mma_kernel(const float* __restrict__ z1, const float* __restrict__ Wf)
{
    extern __shared__ float smem[];
    float* As = smem;                          // 2 x [BM][STRIDE]
    float* Bs = smem + 2 * BM * STRIDE;        // 2 x [FC_BN][STRIDE]

    const int tid = threadIdx.x;
    const int ks = blockIdx.x;                 // k-split 0..7
    const int rbase = blockIdx.y * BM;
    const int kbase = ks * FC_KCHUNK;

    const int warp = tid >> 5, lane = tid & 31;
    const int gid = lane >> 2, tig = lane & 3;
    const int mrow = warp * 16;                // each warp: 16 rows x all 72 cols

    float acc[9][4] = {};

    fc_load(As, Bs, z1, Wf, rbase, kbase, tid);
    asm volatile("cp.async.commit_group;\n");

    for (int kt = 0; kt < FC_KT; ++kt) {
        if (kt + 1 < FC_KT) {
            int nst = (kt + 1) & 1;
            fc_load(As + nst * BM * STRIDE, Bs + nst * FC_BN * STRIDE,
                    z1, Wf, rbase, kbase + (kt + 1) * BK, tid);
            asm volatile("cp.async.commit_group;\n");
            asm volatile("cp.async.wait_group 1;\n");
        } else {
            asm volatile("cp.async.wait_group 0;\n");
        }
        __syncthreads();

        const int st = kt & 1;
        const float* Ast = As + st * BM * STRIDE;
        const float* Bst = Bs + st * FC_BN * STRIDE;

#pragma unroll
        for (int k2 = 0; k2 < 4; ++k2) {
            const int kk = k2 * 8 + tig;
            uint32_t af[4];
            {
                const float* p = Ast + (mrow + gid) * STRIDE + kk;
                af[0] = f2tf(p[0]);
                af[1] = f2tf(p[8 * STRIDE]);
                af[2] = f2tf(p[4]);
                af[3] = f2tf(p[8 * STRIDE + 4]);
            }
#pragma unroll
            for (int ci = 0; ci < 9; ++ci) {
                const float* p = Bst + (ci * 8 + gid) * STRIDE + kk;
                uint32_t bf[2];
                bf[0] = f2tf(p[0]);
                bf[1] = f2tf(p[4]);
                MMA_TF32(acc[ci], af, bf);
            }
        }
        __syncthreads();
    }

    // Store partials
    const int r0 = rbase + mrow + gid;
    float* base0 = g_fcpart + ((size_t)ks * BS_N + r0) * FC_BN;
    float* base1 = base0 + 8 * FC_BN;
#pragma unroll
    for (int ci = 0; ci < 9; ++ci) {
        const int c0 = ci * 8 + 2 * tig;
        base0[c0]     = acc[ci][0];
        base0[c0 + 1] = acc[ci][1];
        base1[c0]     = acc[ci][2];
        base1[c0 + 1] = acc[ci][3];
    }
}

// ---------------------------------------------------------------------------
// Kernel 3: per-class reduce. grid 65 blocks x 256 thr.
// g_const[c] = (sum_k t[k]*W2[c,k]) + 2048*b_fc[c], t[k]=sum_bm g_scratch
// ---------------------------------------------------------------------------
__global__ void reduce_kernel(const float* __restrict__ W_fc,
                              const float* __restrict__ b_fc) {
    __shared__ float red[8];
    const int c = blockIdx.x;
    const int tid = threadIdx.x;
    const float* wr = W_fc + (size_t)c * WFC_COLS + D1;

    float partial = 0.f;
    for (int k = tid; k < N1; k += 256) {
        float t = 0.f;
#pragma unroll
        for (int bm = 0; bm < 16; ++bm) t += g_scratch[bm * N1 + k];
        partial += t * wr[k];
    }
#pragma unroll
    for (int o = 16; o; o >>= 1) partial += __shfl_xor_sync(0xffffffffu, partial, o);
    if ((tid & 31) == 0) red[tid >> 5] = partial;
    __syncthreads();
    if (tid == 0) {
        float s = 0.f;
#pragma unroll
        for (int w = 0; w < 8; ++w) s += red[w];
        g_const[c] = s + 2048.f * b_fc[c];
    }
}

// ---------------------------------------------------------------------------
// Kernel 4: combine. out[i,c] = 2048*sum_s part[s][i][c] + g_const[c]
// ---------------------------------------------------------------------------
__global__ void combine_kernel(float* __restrict__ out) {
    const int idx = blockIdx.x * 256 + threadIdx.x;
    if (idx >= BS_N * NCLS) return;
    const int i = idx / NCLS, c = idx % NCLS;
    float s = 0.f;
#pragma unroll
    for (int sp = 0; sp < FC_KSPLIT; ++sp)
        s += g_fcpart[((size_t)sp * BS_N + i) * FC_BN + c];
    out[idx] = 2048.f * s + g_const[c];
}

// ---------------------------------------------------------------------------
// launch
// ---------------------------------------------------------------------------
#define GEMM1_SMEM ((3 * (BM + BN) * STRIDE + 2 * BN) * (int)sizeof(float))   // 83456
#define FC_SMEM    ((2 * (BM + FC_BN) * STRIDE) * (int)sizeof(float))         // 57600

extern "C" void kernel_launch(void* const* d_in, const int* in_sizes, int n_in,
                              void* d_out, int out_size) {
    const float *z1 = nullptr, *z2 = nullptr, *Wp = nullptr, *bp = nullptr,
                *Wf = nullptr, *bfc = nullptr;
    for (int i = 0; i < n_in; ++i) {
        switch (in_sizes[i]) {
            case BS_N * D1:       z1  = (const float*)d_in[i]; break;
            case BS_N * K1:       z2  = (const float*)d_in[i]; break;
            case N1 * K1:         Wp  = (const float*)d_in[i]; break;
            case N1:              bp  = (const float*)d_in[i]; break;
            case NCLS * WFC_COLS: Wf  = (const float*)d_in[i]; break;
            case NCLS:            bfc = (const float*)d_in[i]; break;
            default: break;
        }
    }

    cudaFuncSetAttribute(gemm1_kernel,
                         cudaFuncAttributeMaxDynamicSharedMemorySize, GEMM1_SMEM);
    cudaFuncSetAttribute(fc_mma_kernel,
                         cudaFuncAttributeMaxDynamicSharedMemorySize, FC_SMEM);

    gemm1_kernel<<<dim3(16, 16), 256, GEMM1_SMEM>>>(z2, Wp, bp);
    fc_mma_kernel<<<dim3(FC_KSPLIT, 16), 256, FC_SMEM>>>(z1, Wf);
    reduce_kernel<<<NCLS, 256>>>(Wf, bfc);
    combine_kernel<<<(BS_N * NCLS + 255) / 256, 256>>>((float*)d_out);
}